// round 3
// baseline (speedup 1.0000x reference)
#include <cuda_runtime.h>
#include <math.h>

#define THREADS 256
#define TB 128
#define PX 68           // pitch (floats) for X/H/W smem rows

// smem layout (floats):
//   buf0: 128*68 = 8704
//   buf1: 128*68 = 8704
//   sB  : big region, max(conv 37808, gru 26496, heads 17796) = 37808
#define SMEM_FLOATS (8704 + 8704 + 37808)
#define SMEM_BYTES  (SMEM_FLOATS * 4)

struct KParams {
    const float* in[32];
    float* out;
    int B;
};

__device__ __forceinline__ float sigmoidf_(float x) { return 1.0f / (1.0f + expf(-x)); }

__device__ __forceinline__ void load_h(float* __restrict__ sH, const float* __restrict__ gmem,
                                       int gs0, int off, int tid)
{
    for (int idx = tid; idx < TB * 64; idx += THREADS) {
        int s = idx >> 6, j = idx & 63;
        sH[s * PX + j] = gmem[(size_t)(gs0 + s) * 256 + off + j];
    }
}

// One GRU cell for TB samples. sX: input x [TB][PX], sH: hidden in, updated in place.
// Loads wih/whh/biases into sB. Writes new h to out_mem (memory_out region).
__device__ __forceinline__ void gru_cell(
    const float* __restrict__ sX, float* __restrict__ sH, float* __restrict__ sB,
    const float* __restrict__ g_wih, const float* __restrict__ g_whh,
    const float* __restrict__ g_bih, const float* __restrict__ g_bhh,
    float* __restrict__ out_mem, int gs0, int cell_off, int tid)
{
    float* Wi = sB;                  // 192*68
    float* Wh = sB + 192 * PX;       // 192*68
    float* bi = sB + 2 * 192 * PX;   // 192
    float* bh = bi + 192;            // 192

    for (int idx = tid; idx < 192 * 64; idx += THREADS) {
        int r = idx >> 6, c = idx & 63;
        Wi[r * PX + c] = g_wih[idx];
        Wh[r * PX + c] = g_whh[idx];
    }
    for (int idx = tid; idx < 192; idx += THREADS) { bi[idx] = g_bih[idx]; bh[idx] = g_bhh[idx]; }
    __syncthreads();

    int ts = tid & 7, tj = tid >> 3;   // ts: sample lane 0..7, tj: 0..31
    for (int sub = 0; sub < 4; ++sub) {
        int sb = sub * 32;
        float acc[4][2][6];
        #pragma unroll
        for (int u = 0; u < 4; u++)
            #pragma unroll
            for (int js = 0; js < 2; js++)
                #pragma unroll
                for (int g2 = 0; g2 < 6; g2++) acc[u][js][g2] = 0.f;

        #pragma unroll 4
        for (int k = 0; k < 64; k += 4) {
            float4 xv[4], hv[4];
            #pragma unroll
            for (int u = 0; u < 4; u++) {
                int s = sb + ts + 8 * u;
                xv[u] = *reinterpret_cast<const float4*>(&sX[s * PX + k]);
                hv[u] = *reinterpret_cast<const float4*>(&sH[s * PX + k]);
            }
            float4 wv[2][6];
            #pragma unroll
            for (int js = 0; js < 2; js++) {
                int j = tj + 32 * js;
                wv[js][0] = *reinterpret_cast<const float4*>(&Wi[(j      ) * PX + k]);
                wv[js][1] = *reinterpret_cast<const float4*>(&Wi[(j + 64 ) * PX + k]);
                wv[js][2] = *reinterpret_cast<const float4*>(&Wi[(j + 128) * PX + k]);
                wv[js][3] = *reinterpret_cast<const float4*>(&Wh[(j      ) * PX + k]);
                wv[js][4] = *reinterpret_cast<const float4*>(&Wh[(j + 64 ) * PX + k]);
                wv[js][5] = *reinterpret_cast<const float4*>(&Wh[(j + 128) * PX + k]);
            }
            #pragma unroll
            for (int u = 0; u < 4; u++) {
                #pragma unroll
                for (int js = 0; js < 2; js++) {
                    #pragma unroll
                    for (int g2 = 0; g2 < 6; g2++) {
                        float4 a = (g2 < 3) ? xv[u] : hv[u];
                        float4 w = wv[js][g2];
                        acc[u][js][g2] += a.x * w.x + a.y * w.y + a.z * w.z + a.w * w.w;
                    }
                }
            }
        }
        __syncthreads();   // all GEMM reads of sH done before in-place writes
        #pragma unroll
        for (int u = 0; u < 4; u++) {
            int s = sb + ts + 8 * u;
            int gs = gs0 + s;
            #pragma unroll
            for (int js = 0; js < 2; js++) {
                int j = tj + 32 * js;
                float r = sigmoidf_(acc[u][js][0] + acc[u][js][3] + bi[j] + bh[j]);
                float z = sigmoidf_(acc[u][js][1] + acc[u][js][4] + bi[64 + j] + bh[64 + j]);
                float n = tanhf(acc[u][js][2] + bi[128 + j] + r * (acc[u][js][5] + bh[128 + j]));
                float h = sH[s * PX + j];
                float hn = (1.f - z) * n + z * h;
                sH[s * PX + j] = hn;
                out_mem[(size_t)gs * 256 + cell_off + j] = hn;
            }
        }
        __syncthreads();   // keep barriers uniform across subtiles
    }
}

__global__ __launch_bounds__(THREADS, 1)
void fused_gru_ac_kernel(KParams P)
{
    extern __shared__ float sm[];
    float* buf0 = sm;
    float* buf1 = sm + 8704;
    float* sB   = sm + 17408;

    const int tid = threadIdx.x;
    const int gs0 = blockIdx.x * TB;
    const int Btot = P.B;

    const float* g_obs = P.in[0];
    const float* g_mem = P.in[1];
    float* out_mem = P.out + (size_t)4 * Btot;   // memory_out region

    // ---------------- conv weights -> smem (once) ----------------
    {
        const float* g;
        g = P.in[2]; for (int i = tid; i < 192;  i += THREADS) sB[i]        = g[i];   // w1
        g = P.in[3]; for (int i = tid; i < 16;   i += THREADS) sB[192 + i]  = g[i];   // b1
        g = P.in[4]; for (int i = tid; i < 2048; i += THREADS) sB[208 + i]  = g[i];   // w2
        g = P.in[5]; for (int i = tid; i < 32;   i += THREADS) sB[2256 + i] = g[i];   // b2
        g = P.in[6]; for (int i = tid; i < 8192; i += THREADS) sB[2288 + i] = g[i];   // w3
        g = P.in[7]; for (int i = tid; i < 64;   i += THREADS) sB[10480 + i] = g[i];  // b3
    }
    float* obsS = sB + 10544;   // 64*149
    float* Pm   = sB + 20080;   // 64*145
    float* o2   = sB + 29360;   // 64*132

    // ---------------- conv stack: 2 passes of 64 samples ----------------
    for (int pass = 0; pass < 2; ++pass) {
        int sg0 = gs0 + pass * 64;
        for (int idx = tid; idx < 64 * 147; idx += THREADS) {
            int s = idx / 147, e = idx - s * 147;
            obsS[s * 149 + e] = g_obs[(size_t)(sg0 + s) * 147 + e];
        }
        __syncthreads();

        int s = tid >> 2, q = tid & 3;   // 4 threads per sample (channel quarters)

        // conv1 (3->16, 2x2) + relu + maxpool2 -> P[16][3][3]
        {
            float w1r[48], b1r[4];
            #pragma unroll
            for (int o4 = 0; o4 < 4; o4++) {
                int o = q * 4 + o4;
                #pragma unroll
                for (int m = 0; m < 12; m++) w1r[o4 * 12 + m] = sB[o * 12 + m];
                b1r[o4] = sB[192 + o];
            }
            for (int i = 0; i < 3; i++)
                for (int j = 0; j < 3; j++) {
                    float xv[27];
                    #pragma unroll
                    for (int c = 0; c < 3; c++)
                        #pragma unroll
                        for (int a = 0; a < 3; a++)
                            #pragma unroll
                            for (int b = 0; b < 3; b++)
                                xv[c * 9 + a * 3 + b] =
                                    obsS[s * 149 + (2 * i + a) * 21 + (2 * j + b) * 3 + c];
                    #pragma unroll
                    for (int o4 = 0; o4 < 4; o4++) {
                        float mx = -1e30f;
                        #pragma unroll
                        for (int pi = 0; pi < 2; pi++)
                            #pragma unroll
                            for (int pj = 0; pj < 2; pj++) {
                                float a0 = b1r[o4];
                                #pragma unroll
                                for (int c = 0; c < 3; c++)
                                    #pragma unroll
                                    for (int ki = 0; ki < 2; ki++)
                                        #pragma unroll
                                        for (int kj = 0; kj < 2; kj++)
                                            a0 += xv[c * 9 + (pi + ki) * 3 + (pj + kj)] *
                                                  w1r[o4 * 12 + c * 4 + ki * 2 + kj];
                                a0 = fmaxf(a0, 0.f);
                                mx = fmaxf(mx, a0);
                            }
                        Pm[s * 145 + (q * 4 + o4) * 9 + i * 3 + j] = mx;
                    }
                }
        }
        __syncthreads();

        // conv2 (16->32, 2x2 on 3x3) + relu -> o2[32][2][2]
        #pragma unroll
        for (int pi = 0; pi < 2; pi++)
            #pragma unroll
            for (int pj = 0; pj < 2; pj++) {
                float xp[64];
                #pragma unroll
                for (int c = 0; c < 16; c++)
                    #pragma unroll
                    for (int a = 0; a < 2; a++)
                        #pragma unroll
                        for (int b = 0; b < 2; b++)
                            xp[c * 4 + a * 2 + b] = Pm[s * 145 + c * 9 + (pi + a) * 3 + (pj + b)];
                for (int o8 = 0; o8 < 8; o8++) {
                    int o = q * 8 + o8;
                    float a0 = sB[2256 + o];
                    #pragma unroll
                    for (int kk = 0; kk < 16; kk++) {
                        float4 w = *reinterpret_cast<const float4*>(&sB[208 + o * 64 + kk * 4]);
                        a0 += xp[kk * 4] * w.x + xp[kk * 4 + 1] * w.y +
                              xp[kk * 4 + 2] * w.z + xp[kk * 4 + 3] * w.w;
                    }
                    o2[s * 132 + o * 4 + pi * 2 + pj] = fmaxf(a0, 0.f);
                }
            }
        __syncthreads();

        // conv3 (32->64, 2x2 on 2x2) + relu -> x[64] into buf0
        for (int o16 = 0; o16 < 16; o16++) {
            int o = q * 16 + o16;
            float a0 = sB[10480 + o];
            #pragma unroll
            for (int kk = 0; kk < 32; kk++) {
                float4 w  = *reinterpret_cast<const float4*>(&sB[2288 + o * 128 + kk * 4]);
                float4 x4 = *reinterpret_cast<const float4*>(&o2[s * 132 + kk * 4]);
                a0 += x4.x * w.x + x4.y * w.y + x4.z * w.z + x4.w * w.w;
            }
            buf0[(pass * 64 + s) * PX + o] = fmaxf(a0, 0.f);
        }
        __syncthreads();
    }

    // ---------------- 4 GRU cells ----------------
    float* Xp = buf0;
    float* Hp = buf1;

    load_h(Hp, g_mem, gs0, 0, tid);
    gru_cell(Xp, Hp, sB, P.in[8],  P.in[9],  P.in[10], P.in[11], out_mem, gs0, 0,   tid);
    { float* t = Xp; Xp = Hp; Hp = t; }

    load_h(Hp, g_mem, gs0, 64, tid);
    gru_cell(Xp, Hp, sB, P.in[12], P.in[13], P.in[14], P.in[15], out_mem, gs0, 64,  tid);
    { float* t = Xp; Xp = Hp; Hp = t; }

    load_h(Hp, g_mem, gs0, 128, tid);
    gru_cell(Xp, Hp, sB, P.in[16], P.in[17], P.in[18], P.in[19], out_mem, gs0, 128, tid);
    { float* t = Xp; Xp = Hp; Hp = t; }

    load_h(Hp, g_mem, gs0, 192, tid);
    gru_cell(Xp, Hp, sB, P.in[20], P.in[21], P.in[22], P.in[23], out_mem, gs0, 192, tid);
    { float* t = Xp; Xp = Hp; Hp = t; }
    // Xp = embedding [TB][PX], Hp = scratch

    // ---------------- heads ----------------
    float* HW  = sB;            // 128 rows x PX: rows 0..63 actor_w1, 64..127 critic_w1
    float* ab1 = sB + 8704;     // 64
    float* cb1 = sB + 8768;     // 64
    float* aw2 = sB + 8832;     // 3*64
    float* ab2 = sB + 9024;     // 3
    float* cw2 = sB + 9027;     // 64
    float* cb2 = sB + 9091;     // 1
    float* C1  = sB + 9092;     // 128 x PX

    {
        const float* ga = P.in[24];  // actor_w1 [64][64]
        const float* gc = P.in[28];  // critic_w1 [64][64]
        for (int idx = tid; idx < 64 * 64; idx += THREADS) {
            int r = idx >> 6, c = idx & 63;
            HW[r * PX + c]        = ga[idx];
            HW[(64 + r) * PX + c] = gc[idx];
        }
        const float* g;
        g = P.in[25]; for (int i = tid; i < 64;  i += THREADS) ab1[i] = g[i];
        g = P.in[29]; for (int i = tid; i < 64;  i += THREADS) cb1[i] = g[i];
        g = P.in[26]; for (int i = tid; i < 192; i += THREADS) aw2[i] = g[i];
        g = P.in[27]; for (int i = tid; i < 3;   i += THREADS) ab2[i] = g[i];
        g = P.in[30]; for (int i = tid; i < 64;  i += THREADS) cw2[i] = g[i];
        g = P.in[31]; if (tid == 0) cb2[0] = g[0];
    }
    __syncthreads();

    // pass1: a1 = relu(emb @ actor_w1^T + b), c1 = relu(emb @ critic_w1^T + b)
    {
        int ts = tid & 7, tj = tid >> 3;
        for (int sub = 0; sub < 4; ++sub) {
            int sb = sub * 32;
            float acc[4][4];
            #pragma unroll
            for (int u = 0; u < 4; u++)
                #pragma unroll
                for (int m = 0; m < 4; m++) acc[u][m] = 0.f;

            #pragma unroll 4
            for (int k = 0; k < 64; k += 4) {
                float4 xv[4];
                #pragma unroll
                for (int u = 0; u < 4; u++) {
                    int s = sb + ts + 8 * u;
                    xv[u] = *reinterpret_cast<const float4*>(&Xp[s * PX + k]);
                }
                float4 wv[4];
                #pragma unroll
                for (int m = 0; m < 4; m++)
                    wv[m] = *reinterpret_cast<const float4*>(&HW[(tj + 32 * m) * PX + k]);
                #pragma unroll
                for (int u = 0; u < 4; u++)
                    #pragma unroll
                    for (int m = 0; m < 4; m++)
                        acc[u][m] += xv[u].x * wv[m].x + xv[u].y * wv[m].y +
                                     xv[u].z * wv[m].z + xv[u].w * wv[m].w;
            }
            #pragma unroll
            for (int u = 0; u < 4; u++) {
                int s = sb + ts + 8 * u;
                #pragma unroll
                for (int m = 0; m < 4; m++) {
                    int j = tj + 32 * m;
                    float v = acc[u][m] + (j < 64 ? ab1[j] : cb1[j - 64]);
                    v = fmaxf(v, 0.f);
                    if (j < 64) Hp[s * PX + j] = v;
                    else        C1[s * PX + (j - 64)] = v;
                }
            }
        }
    }
    __syncthreads();

    // final: logits + log_softmax (even threads), value (odd threads)
    {
        int s2 = tid >> 1;
        int gs = gs0 + s2;
        if ((tid & 1) == 0) {
            float l0 = ab2[0], l1 = ab2[1], l2 = ab2[2];
            #pragma unroll 8
            for (int k = 0; k < 64; k++) {
                float a = Hp[s2 * PX + k];
                l0 += a * aw2[k];
                l1 += a * aw2[64 + k];
                l2 += a * aw2[128 + k];
            }
            float mx = fmaxf(l0, fmaxf(l1, l2));
            float lse = mx + logf(expf(l0 - mx) + expf(l1 - mx) + expf(l2 - mx));
            P.out[(size_t)gs * 3 + 0] = l0 - lse;
            P.out[(size_t)gs * 3 + 1] = l1 - lse;
            P.out[(size_t)gs * 3 + 2] = l2 - lse;
        } else {
            float v = cb2[0];
            #pragma unroll 8
            for (int k = 0; k < 64; k++) v += C1[s2 * PX + k] * cw2[k];
            P.out[(size_t)3 * Btot + gs] = v;
        }
    }
}

extern "C" void kernel_launch(void* const* d_in, const int* in_sizes, int n_in,
                              void* d_out, int out_size)
{
    KParams P;
    for (int i = 0; i < 32; i++) P.in[i] = (const float*)d_in[i];
    P.out = (float*)d_out;
    P.B = in_sizes[1] / 256;   // memory is [B, 256]

    cudaFuncSetAttribute(fused_gru_ac_kernel,
                         cudaFuncAttributeMaxDynamicSharedMemorySize, SMEM_BYTES);

    int grid = P.B / TB;
    fused_gru_ac_kernel<<<grid, THREADS, SMEM_BYTES>>>(P);
}